// round 6
// baseline (speedup 1.0000x reference)
#include <cuda_runtime.h>
#include <math.h>

#define B_ 2
#define H_ 8
#define NSEQ 2048
#define DDIM 64
#define BH (B_*H_)
#define NWORDS 3126               // ceil(100001/32)

typedef unsigned long long u64;

__device__ float KT_g[BH * DDIM * NSEQ];   // 8MB transposed K: [bh][d][n]

__device__ __forceinline__ u64 pk2(float x, float y) {
    u64 u; asm("mov.b64 %0,{%1,%2};" : "=l"(u) : "f"(x), "f"(y)); return u;
}
__device__ __forceinline__ float2 up2(u64 u) {
    float2 r; asm("mov.b64 {%0,%1},%2;" : "=f"(r.x), "=f"(r.y) : "l"(u)); return r;
}
__device__ __forceinline__ void fma2(u64 &d, u64 a, u64 b) {
    asm("fma.rn.f32x2 %0,%1,%2,%3;" : "=l"(d) : "l"(a), "l"(b), "l"(d));
}
__device__ __forceinline__ void cpa16(unsigned dst, const void* src) {
    asm volatile("cp.async.cg.shared.global [%0], [%1], 16;" :: "r"(dst), "l"(src));
}
__device__ __forceinline__ void cp_commit() { asm volatile("cp.async.commit_group;"); }
__device__ __forceinline__ void cp_wait0()  { asm volatile("cp.async.wait_group 0;" ::: "memory"); }
__device__ __forceinline__ void cp_wait1()  { asm volatile("cp.async.wait_group 1;" ::: "memory"); }

// ============================================================================
// Kernel T: KT[bh][d][n] = K[bh][n][d]
// ============================================================================
__global__ void transpose_k(const float* __restrict__ k) {
    __shared__ float t[32][33];
    const int bh = blockIdx.z;
    const int n0 = blockIdx.x * 32, d0 = blockIdx.y * 32;
    const int x = threadIdx.x, y = threadIdx.y;       // block (32,8)
    const size_t base = (size_t)bh * NSEQ * DDIM;
    #pragma unroll
    for (int j = 0; j < 4; j++)
        t[y + 8*j][x] = k[base + (size_t)(n0 + y + 8*j) * DDIM + d0 + x];
    __syncthreads();
    float* kt = KT_g + (size_t)bh * DDIM * NSEQ;
    #pragma unroll
    for (int j = 0; j < 4; j++)
        kt[(size_t)(d0 + y + 8*j) * NSEQ + n0 + x] = t[x][y + 8*j];
}

// ============================================================================
// Kernel A: QK^T -> rowmax -> exp/round -> distinct-sum denom -> attn_p
// 16 q-rows, 512 threads, thread tile 16q x 4n (acc packed f32x2 over q-pairs)
// ============================================================================
#define QROWS 16
#define NTA 512
#define DT 4
#define NDT (DDIM/DT)        // 16
#define S_F (QROWS*NSEQ)     // 32768 floats
#define QP_F (64*8*2)        // qp u64[64][8] as floats
#define KTS_F (2*DT*NSEQ)    // 16384 floats

__global__ __launch_bounds__(NTA, 1)
void sdpa_scores_kernel(const float* __restrict__ q,
                        float* __restrict__ attn_out) {
    extern __shared__ float sm[];
    float* s   = sm;                         // [16][2048]
    u64*   qp  = (u64*)(s + S_F);            // [64 d][8 q-pair]
    float* kts = (float*)(qp + 64*8);        // 2 x [DT][2048]
    unsigned* bmp = (unsigned*)kts;          // aliased (phase 4)
    u64* rowSum = (u64*)(kts + KTS_F);
    float* scale = (float*)(rowSum + QROWS);

    const int tid  = threadIdx.x;
    const int w    = tid >> 5;
    const int lane = tid & 31;
    const int bh   = blockIdx.y;
    const int row0 = blockIdx.x * QROWS;
    const float* kt = KT_g + (size_t)bh * DDIM * NSEQ;
    const unsigned ktsu = (unsigned)__cvta_generic_to_shared(kts);

    // build packed q-pairs: qp[d][i] = (q[2i][d], q[2i+1][d]) * 0.125
    for (int idx = tid; idx < 64*8; idx += NTA) {
        int d = idx >> 3, qi = idx & 7;
        float lo = q[((size_t)bh*NSEQ + row0 + 2*qi    ) * DDIM + d] * 0.125f;
        float hi = q[((size_t)bh*NSEQ + row0 + 2*qi + 1) * DDIM + d] * 0.125f;
        qp[idx] = pk2(lo, hi);
    }
    if (tid < QROWS) rowSum[tid] = 0ull;

    u64 acc[8][4];
    #pragma unroll
    for (int i = 0; i < 8; i++)
        #pragma unroll
        for (int n = 0; n < 4; n++) acc[i][n] = 0ull;

    // issue stage 0
    {
        #pragma unroll
        for (int j = 0; j < 4; j++) {
            int idx = tid + j*NTA;                 // 0..2047 f4
            int rr = idx >> 9, c4 = idx & 511;
            cpa16(ktsu + 4u*(rr*NSEQ + c4*4),
                  kt + (size_t)rr*NSEQ + c4*4);
        }
        cp_commit();
    }

    for (int t = 0; t < NDT; t++) {
        if (t + 1 < NDT) {
            int buf = (t + 1) & 1;
            #pragma unroll
            for (int j = 0; j < 4; j++) {
                int idx = tid + j*NTA;
                int rr = idx >> 9, c4 = idx & 511;
                cpa16(ktsu + 4u*(buf*DT*NSEQ + rr*NSEQ + c4*4),
                      kt + (size_t)((t+1)*DT + rr)*NSEQ + c4*4);
            }
            cp_commit(); cp_wait1();
        } else cp_wait0();
        __syncthreads();

        const float* kb = kts + (t & 1)*DT*NSEQ;
        #pragma unroll
        for (int dd = 0; dd < DT; dd++) {
            int d = t*DT + dd;
            float4 kf = *(const float4*)&kb[dd*NSEQ + 4*tid];
            u64 k0 = pk2(kf.x, kf.x), k1 = pk2(kf.y, kf.y);
            u64 k2 = pk2(kf.z, kf.z), k3 = pk2(kf.w, kf.w);
            const ulonglong2* qq = (const ulonglong2*)(qp + d*8);
            ulonglong2 qA = qq[0], qB = qq[1], qC = qq[2], qD = qq[3];
            fma2(acc[0][0],qA.x,k0); fma2(acc[0][1],qA.x,k1); fma2(acc[0][2],qA.x,k2); fma2(acc[0][3],qA.x,k3);
            fma2(acc[1][0],qA.y,k0); fma2(acc[1][1],qA.y,k1); fma2(acc[1][2],qA.y,k2); fma2(acc[1][3],qA.y,k3);
            fma2(acc[2][0],qB.x,k0); fma2(acc[2][1],qB.x,k1); fma2(acc[2][2],qB.x,k2); fma2(acc[2][3],qB.x,k3);
            fma2(acc[3][0],qB.y,k0); fma2(acc[3][1],qB.y,k1); fma2(acc[3][2],qB.y,k2); fma2(acc[3][3],qB.y,k3);
            fma2(acc[4][0],qC.x,k0); fma2(acc[4][1],qC.x,k1); fma2(acc[4][2],qC.x,k2); fma2(acc[4][3],qC.x,k3);
            fma2(acc[5][0],qC.y,k0); fma2(acc[5][1],qC.y,k1); fma2(acc[5][2],qC.y,k2); fma2(acc[5][3],qC.y,k3);
            fma2(acc[6][0],qD.x,k0); fma2(acc[6][1],qD.x,k1); fma2(acc[6][2],qD.x,k2); fma2(acc[6][3],qD.x,k3);
            fma2(acc[7][0],qD.y,k0); fma2(acc[7][1],qD.y,k1); fma2(acc[7][2],qD.y,k2); fma2(acc[7][3],qD.y,k3);
        }
        __syncthreads();
    }

    // acc -> s  (rows 2i and 2i+1, cols 4*tid..)
    #pragma unroll
    for (int i = 0; i < 8; i++) {
        float2 f0 = up2(acc[i][0]), f1 = up2(acc[i][1]);
        float2 f2 = up2(acc[i][2]), f3 = up2(acc[i][3]);
        float4 lo; lo.x = f0.x; lo.y = f1.x; lo.z = f2.x; lo.w = f3.x;
        float4 hi; hi.x = f0.y; hi.y = f1.y; hi.z = f2.y; hi.w = f3.y;
        *(float4*)&s[(2*i  )*NSEQ + 4*tid] = lo;
        *(float4*)&s[(2*i+1)*NSEQ + 4*tid] = hi;
    }
    __syncthreads();

    // phase 2+3: warp w owns row w
    {
        float4* srow4 = (float4*)&s[w*NSEQ];
        float mx = -INFINITY;
        for (int i = lane; i < NSEQ/4; i += 32) {
            float4 vv = srow4[i];
            mx = fmaxf(mx, fmaxf(fmaxf(vv.x, vv.y), fmaxf(vv.z, vv.w)));
        }
        #pragma unroll
        for (int o = 16; o > 0; o >>= 1) mx = fmaxf(mx, __shfl_xor_sync(0xffffffffu, mx, o));
        for (int i = lane; i < NSEQ/4; i += 32) {
            float4 vv = srow4[i];
            vv.x = rintf(expf(vv.x - mx) * 100000.0f);
            vv.y = rintf(expf(vv.y - mx) * 100000.0f);
            vv.z = rintf(expf(vv.z - mx) * 100000.0f);
            vv.w = rintf(expf(vv.w - mx) * 100000.0f);
            srow4[i] = vv;
        }
    }
    __syncthreads();

    // init bitmap (aliased over KT stage buffers)
    for (int i = tid; i < NWORDS; i += NTA) bmp[i] = 0u;
    __syncthreads();

    // phase 4: distinct-sum denominator (one f4 per thread per row)
    for (int r = 0; r < QROWS; r++) {
        float4 vv = *(const float4*)&s[r*NSEQ + 4*tid];
        float vals[4] = {vv.x, vv.y, vv.z, vv.w};
        u64 local = 0ull;
        #pragma unroll
        for (int e = 0; e < 4; e++) {
            int ri = (int)vals[e];
            unsigned peers = __match_any_sync(0xffffffffu, ri);
            if (ri != 0 && (int)(__ffs(peers) - 1) == lane) {
                unsigned bit = 1u << (ri & 31);
                unsigned old = atomicOr(&bmp[ri >> 5], bit);
                if (!(old & bit)) local += (unsigned)ri;
            }
        }
        #pragma unroll
        for (int o = 16; o > 0; o >>= 1) local += __shfl_xor_sync(0xffffffffu, local, o);
        if (lane == 0 && local) atomicAdd(&rowSum[r], local);
        __syncthreads();
        #pragma unroll
        for (int e = 0; e < 4; e++) bmp[((int)vals[e]) >> 5] = 0u;
        __syncthreads();
    }
    if (tid < QROWS) scale[tid] = 1.0f / (float)rowSum[tid];
    __syncthreads();

    // phase 5: write attn_p (warp w -> row w)
    {
        float sc = scale[w];
        float4* dst4 = (float4*)(attn_out + ((size_t)bh*NSEQ + row0 + w) * NSEQ);
        const float4* src4 = (const float4*)&s[w*NSEQ];
        for (int i = lane; i < NSEQ/4; i += 32) {
            float4 vv = src4[i];
            vv.x *= sc; vv.y *= sc; vv.z *= sc; vv.w *= sc;
            dst4[i] = vv;
        }
    }
}

// ============================================================================
// Kernel B: out = attn_p @ V. QB=64 block, 4q x 4d per thread, 3 CTAs/SM.
// ============================================================================
#define QB 64
#define PADB 68
#define KSTEP 64
#define NKT (NSEQ/KSTEP)
#define STAGE_F (QB*PADB + KSTEP*PADB)

__global__ __launch_bounds__(256, 3)
void pv_kernel(const float* __restrict__ attn,
               const float* __restrict__ v,
               float* __restrict__ out) {
    extern __shared__ float smb[];
    const int tid = threadIdx.x;
    const int tx = tid & 15;       // d cols 4*tx..
    const int ty = tid >> 4;       // q rows 4*ty..
    const int bh = blockIdx.y;
    const int row0 = blockIdx.x * QB;
    const size_t abase = ((size_t)bh * NSEQ + row0) * NSEQ;
    const size_t vbase = (size_t)bh * NSEQ * DDIM;
    const unsigned smbu = (unsigned)__cvta_generic_to_shared(smb);

    auto issue_stage = [&](int t, int buf) {
        unsigned pbase = smbu + 4u*buf*STAGE_F;
        unsigned vbse  = pbase + 4u*QB*PADB;
        #pragma unroll
        for (int j = 0; j < 4; j++) {
            int idx = tid + j*256;             // 0..1023
            int rr = idx >> 4, c4 = idx & 15;
            cpa16(pbase + 4u*(rr*PADB + c4*4),
                  attn + abase + (size_t)rr*NSEQ + t*KSTEP + c4*4);
            cpa16(vbse + 4u*(rr*PADB + c4*4),
                  v + vbase + (size_t)(t*KSTEP + rr)*DDIM + c4*4);
        }
        cp_commit();
    };

    u64 acc[4][2];
    #pragma unroll
    for (int i = 0; i < 4; i++) { acc[i][0] = 0ull; acc[i][1] = 0ull; }

    issue_stage(0, 0);
    for (int t = 0; t < NKT; t++) {
        if (t + 1 < NKT) { issue_stage(t + 1, (t + 1) & 1); cp_wait1(); }
        else cp_wait0();
        __syncthreads();
        const float* Pt = smb + (t & 1)*STAGE_F;
        const float* Vt = Pt + QB*PADB;
        #pragma unroll 4
        for (int kg = 0; kg < KSTEP/4; kg++) {
            int k0 = kg*4;
            float4 v0 = *(const float4*)&Vt[(k0+0)*PADB + tx*4];
            float4 v1 = *(const float4*)&Vt[(k0+1)*PADB + tx*4];
            float4 v2 = *(const float4*)&Vt[(k0+2)*PADB + tx*4];
            float4 v3 = *(const float4*)&Vt[(k0+3)*PADB + tx*4];
            u64 v0l = pk2(v0.x,v0.y), v0h = pk2(v0.z,v0.w);
            u64 v1l = pk2(v1.x,v1.y), v1h = pk2(v1.z,v1.w);
            u64 v2l = pk2(v2.x,v2.y), v2h = pk2(v2.z,v2.w);
            u64 v3l = pk2(v3.x,v3.y), v3h = pk2(v3.z,v3.w);
            #pragma unroll
            for (int i = 0; i < 4; i++) {
                float4 p = *(const float4*)&Pt[(ty*4+i)*PADB + k0];
                fma2(acc[i][0], pk2(p.x,p.x), v0l); fma2(acc[i][1], pk2(p.x,p.x), v0h);
                fma2(acc[i][0], pk2(p.y,p.y), v1l); fma2(acc[i][1], pk2(p.y,p.y), v1h);
                fma2(acc[i][0], pk2(p.z,p.z), v2l); fma2(acc[i][1], pk2(p.z,p.z), v2h);
                fma2(acc[i][0], pk2(p.w,p.w), v3l); fma2(acc[i][1], pk2(p.w,p.w), v3h);
            }
        }
        __syncthreads();
    }

    #pragma unroll
    for (int i = 0; i < 4; i++) {
        float2 lo = up2(acc[i][0]), hi = up2(acc[i][1]);
        float4 r; r.x = lo.x; r.y = lo.y; r.z = hi.x; r.w = hi.y;
        *(float4*)&out[((size_t)bh*NSEQ + row0 + ty*4 + i)*DDIM + tx*4] = r;
    }
}

extern "C" void kernel_launch(void* const* d_in, const int* in_sizes, int n_in,
                              void* d_out, int out_size) {
    const float* q = (const float*)d_in[0];
    const float* k = (const float*)d_in[1];
    const float* v = (const float*)d_in[2];
    float* out = (float*)d_out;                                 // [B,H,N,D]
    float* attn_out = out + (size_t)B_ * H_ * NSEQ * DDIM;      // [B,H,N,N]

    dim3 gridT(NSEQ/32, DDIM/32, BH);
    transpose_k<<<gridT, dim3(32, 8)>>>(k);

    const int smemA = (S_F + QP_F + KTS_F) * 4 + QROWS*8 + QROWS*4;
    cudaFuncSetAttribute(sdpa_scores_kernel,
                         cudaFuncAttributeMaxDynamicSharedMemorySize, smemA);
    dim3 gridA(NSEQ / QROWS, BH);
    sdpa_scores_kernel<<<gridA, NTA, smemA>>>(q, attn_out);

    const int smemB = 2 * STAGE_F * 4;
    cudaFuncSetAttribute(pv_kernel,
                         cudaFuncAttributeMaxDynamicSharedMemorySize, smemB);
    dim3 gridB(NSEQ / QB, BH);
    pv_kernel<<<gridB, 256, smemB>>>(attn_out, v, out);
}

// round 8
// speedup vs baseline: 1.1270x; 1.1270x over previous
#include <cuda_runtime.h>
#include <math.h>

#define B_ 2
#define H_ 8
#define NSEQ 2048
#define DDIM 64
#define BH (B_*H_)
#define NWORDS 3126               // ceil(100001/32)

typedef unsigned long long u64;

__device__ float KT_g[BH * DDIM * NSEQ];   // 8MB transposed K: [bh][d][n]

__device__ __forceinline__ u64 pk2(float x, float y) {
    u64 u; asm("mov.b64 %0,{%1,%2};" : "=l"(u) : "f"(x), "f"(y)); return u;
}
__device__ __forceinline__ float2 up2(u64 u) {
    float2 r; asm("mov.b64 {%0,%1},%2;" : "=f"(r.x), "=f"(r.y) : "l"(u)); return r;
}
__device__ __forceinline__ void fma2(u64 &d, u64 a, u64 b) {
    asm("fma.rn.f32x2 %0,%1,%2,%3;" : "=l"(d) : "l"(a), "l"(b), "l"(d));
}
__device__ __forceinline__ void cpa16(unsigned dst, const void* src) {
    asm volatile("cp.async.cg.shared.global [%0], [%1], 16;" :: "r"(dst), "l"(src));
}
__device__ __forceinline__ void cp_commit() { asm volatile("cp.async.commit_group;"); }
__device__ __forceinline__ void cp_wait0()  { asm volatile("cp.async.wait_group 0;" ::: "memory"); }
__device__ __forceinline__ void cp_wait1()  { asm volatile("cp.async.wait_group 1;" ::: "memory"); }

// ============================================================================
// Kernel T: KT[bh][d][n] = K[bh][n][d]
// ============================================================================
__global__ void transpose_k(const float* __restrict__ k) {
    __shared__ float t[32][33];
    const int bh = blockIdx.z;
    const int n0 = blockIdx.x * 32, d0 = blockIdx.y * 32;
    const int x = threadIdx.x, y = threadIdx.y;       // block (32,8)
    const size_t base = (size_t)bh * NSEQ * DDIM;
    #pragma unroll
    for (int j = 0; j < 4; j++)
        t[y + 8*j][x] = k[base + (size_t)(n0 + y + 8*j) * DDIM + d0 + x];
    __syncthreads();
    float* kt = KT_g + (size_t)bh * DDIM * NSEQ;
    #pragma unroll
    for (int j = 0; j < 4; j++)
        kt[(size_t)(d0 + y + 8*j) * NSEQ + n0 + x] = t[x][y + 8*j];
}

// ============================================================================
// Kernel A: QK^T -> rowmax -> exp/round -> distinct-sum denom -> attn_p
// 256 threads, ROWS=8, ~98KB smem -> 2 CTAs/SM.
// Thread tile: 4 q-pairs x 8 n, acc in 32 packed f32x2 regs.
// ============================================================================
#define ROWS 8
#define NTA 256
#define DT 2
#define NDT (DDIM/DT)        // 32 stages
#define S_F (ROWS*NSEQ)      // 16384 floats = 64KB
#define QP_U (DDIM*4)        // qp u64[64 d][4 pair]
#define KTS_F (2*DT*NSEQ)    // 8192 floats = 32KB (2 stages)

__global__ __launch_bounds__(NTA, 2)
void sdpa_scores_kernel(const float* __restrict__ q,
                        float* __restrict__ attn_out) {
    extern __shared__ float sm[];
    float* s   = sm;                          // [8][2048]
    u64*   qp  = (u64*)(s + S_F);             // [64 d][4 q-pair]
    float* kts = (float*)(qp + QP_U);         // 2 x [DT][2048]
    unsigned* bmp = (unsigned*)kts;           // aliased (phase 4 only)
    u64* rowSum = (u64*)(kts + KTS_F);
    float* scale = (float*)(rowSum + ROWS);

    const int tid  = threadIdx.x;
    const int w    = tid >> 5;
    const int lane = tid & 31;
    const int bh   = blockIdx.y;
    const int row0 = blockIdx.x * ROWS;
    const float* kt = KT_g + (size_t)bh * DDIM * NSEQ;
    const unsigned ktsu = (unsigned)__cvta_generic_to_shared(kts);

    // build packed q-pairs: qp[d][i] = (q[2i][d], q[2i+1][d]) * 0.125
    {
        int d = tid >> 2, pi = tid & 3;
        float lo = q[((size_t)bh*NSEQ + row0 + 2*pi    ) * DDIM + d] * 0.125f;
        float hi = q[((size_t)bh*NSEQ + row0 + 2*pi + 1) * DDIM + d] * 0.125f;
        qp[tid] = pk2(lo, hi);
    }
    if (tid < ROWS) rowSum[tid] = 0ull;

    // issue stage 0 (d rows 0..DT-1): 1024 f4 over 256 threads
    {
        #pragma unroll
        for (int j = 0; j < 4; j++) {
            int idx = tid + j*NTA;
            int rr = idx >> 9, c4 = idx & 511;
            cpa16(ktsu + 4u*(rr*NSEQ + c4*4), kt + (size_t)rr*NSEQ + c4*4);
        }
        cp_commit();
    }

    u64 acc[4][8];
    #pragma unroll
    for (int i = 0; i < 4; i++)
        #pragma unroll
        for (int n = 0; n < 8; n++) acc[i][n] = 0ull;

    for (int t = 0; t < NDT; t++) {
        if (t + 1 < NDT) {
            int buf = (t + 1) & 1;
            #pragma unroll
            for (int j = 0; j < 4; j++) {
                int idx = tid + j*NTA;
                int rr = idx >> 9, c4 = idx & 511;
                cpa16(ktsu + 4u*(buf*DT*NSEQ + rr*NSEQ + c4*4),
                      kt + (size_t)((t+1)*DT + rr)*NSEQ + c4*4);
            }
            cp_commit(); cp_wait1();
        } else cp_wait0();
        __syncthreads();

        const float* kb = kts + (t & 1)*DT*NSEQ;
        #pragma unroll
        for (int dd = 0; dd < DT; dd++) {
            const int d = t*DT + dd;
            float4 kf0 = *(const float4*)&kb[dd*NSEQ + 8*tid];
            float4 kf1 = *(const float4*)&kb[dd*NSEQ + 8*tid + 4];
            const ulonglong2* qq = (const ulonglong2*)(qp + d*4);
            ulonglong2 qA = qq[0], qB = qq[1];
            u64 k0 = pk2(kf0.x,kf0.x), k1 = pk2(kf0.y,kf0.y);
            u64 k2 = pk2(kf0.z,kf0.z), k3 = pk2(kf0.w,kf0.w);
            u64 k4 = pk2(kf1.x,kf1.x), k5 = pk2(kf1.y,kf1.y);
            u64 k6 = pk2(kf1.z,kf1.z), k7 = pk2(kf1.w,kf1.w);
            fma2(acc[0][0],qA.x,k0); fma2(acc[0][1],qA.x,k1); fma2(acc[0][2],qA.x,k2); fma2(acc[0][3],qA.x,k3);
            fma2(acc[0][4],qA.x,k4); fma2(acc[0][5],qA.x,k5); fma2(acc[0][6],qA.x,k6); fma2(acc[0][7],qA.x,k7);
            fma2(acc[1][0],qA.y,k0); fma2(acc[1][1],qA.y,k1); fma2(acc[1][2],qA.y,k2); fma2(acc[1][3],qA.y,k3);
            fma2(acc[1][4],qA.y,k4); fma2(acc[1][5],qA.y,k5); fma2(acc[1][6],qA.y,k6); fma2(acc[1][7],qA.y,k7);
            fma2(acc[2][0],qB.x,k0); fma2(acc[2][1],qB.x,k1); fma2(acc[2][2],qB.x,k2); fma2(acc[2][3],qB.x,k3);
            fma2(acc[2][4],qB.x,k4); fma2(acc[2][5],qB.x,k5); fma2(acc[2][6],qB.x,k6); fma2(acc[2][7],qB.x,k7);
            fma2(acc[3][0],qB.y,k0); fma2(acc[3][1],qB.y,k1); fma2(acc[3][2],qB.y,k2); fma2(acc[3][3],qB.y,k3);
            fma2(acc[3][4],qB.y,k4); fma2(acc[3][5],qB.y,k5); fma2(acc[3][6],qB.y,k6); fma2(acc[3][7],qB.y,k7);
        }
        __syncthreads();
    }

    // acc -> s : rows (2i, 2i+1), cols 8*tid..8*tid+7
    #pragma unroll
    for (int i = 0; i < 4; i++) {
        float2 f0 = up2(acc[i][0]), f1 = up2(acc[i][1]);
        float2 f2 = up2(acc[i][2]), f3 = up2(acc[i][3]);
        float2 f4 = up2(acc[i][4]), f5 = up2(acc[i][5]);
        float2 f6 = up2(acc[i][6]), f7 = up2(acc[i][7]);
        float4 a, b;
        a.x=f0.x; a.y=f1.x; a.z=f2.x; a.w=f3.x;
        b.x=f4.x; b.y=f5.x; b.z=f6.x; b.w=f7.x;
        *(float4*)&s[(2*i)*NSEQ + 8*tid] = a;
        *(float4*)&s[(2*i)*NSEQ + 8*tid + 4] = b;
        a.x=f0.y; a.y=f1.y; a.z=f2.y; a.w=f3.y;
        b.x=f4.y; b.y=f5.y; b.z=f6.y; b.w=f7.y;
        *(float4*)&s[(2*i+1)*NSEQ + 8*tid] = a;
        *(float4*)&s[(2*i+1)*NSEQ + 8*tid + 4] = b;
    }
    __syncthreads();

    // phase 2+3: warp w owns row w: max, exp, round-to-int
    {
        float4* srow4 = (float4*)&s[w*NSEQ];
        float mx = -INFINITY;
        for (int i = lane; i < NSEQ/4; i += 32) {
            float4 vv = srow4[i];
            mx = fmaxf(mx, fmaxf(fmaxf(vv.x, vv.y), fmaxf(vv.z, vv.w)));
        }
        #pragma unroll
        for (int o = 16; o > 0; o >>= 1) mx = fmaxf(mx, __shfl_xor_sync(0xffffffffu, mx, o));
        for (int i = lane; i < NSEQ/4; i += 32) {
            float4 vv = srow4[i];
            vv.x = rintf(expf(vv.x - mx) * 100000.0f);
            vv.y = rintf(expf(vv.y - mx) * 100000.0f);
            vv.z = rintf(expf(vv.z - mx) * 100000.0f);
            vv.w = rintf(expf(vv.w - mx) * 100000.0f);
            srow4[i] = vv;
        }
    }
    __syncthreads();

    // init bitmap (aliased over kts stages; 12.5KB < 32KB)
    for (int i = tid; i < NWORDS; i += NTA) bmp[i] = 0u;
    __syncthreads();

    // phase 4: distinct-sum denominator (8 elems/thread/row), warp dedup
    for (int r = 0; r < ROWS; r++) {
        const float4* row4 = (const float4*)&s[r*NSEQ];
        float4 va = row4[2*tid], vb = row4[2*tid + 1];
        float vals[8] = {va.x, va.y, va.z, va.w, vb.x, vb.y, vb.z, vb.w};
        u64 local = 0ull;
        #pragma unroll
        for (int e = 0; e < 8; e++) {
            int ri = (int)vals[e];
            unsigned peers = __match_any_sync(0xffffffffu, ri);
            if (ri != 0 && (int)(__ffs(peers) - 1) == lane) {
                unsigned bit = 1u << (ri & 31);
                unsigned old = atomicOr(&bmp[ri >> 5], bit);
                if (!(old & bit)) local += (unsigned)ri;
            }
        }
        #pragma unroll
        for (int o = 16; o > 0; o >>= 1) local += __shfl_xor_sync(0xffffffffu, local, o);
        if (lane == 0 && local) atomicAdd(&rowSum[r], local);
        __syncthreads();
        #pragma unroll
        for (int e = 0; e < 8; e++) bmp[((int)vals[e]) >> 5] = 0u;
        __syncthreads();
    }
    if (tid < ROWS) scale[tid] = 1.0f / (float)rowSum[tid];
    __syncthreads();

    // phase 5: write attn_p (warp w -> row w)
    {
        float sc = scale[w];
        float4* dst4 = (float4*)(attn_out + ((size_t)bh*NSEQ + row0 + w) * NSEQ);
        const float4* src4 = (const float4*)&s[w*NSEQ];
        for (int i = lane; i < NSEQ/4; i += 32) {
            float4 vv = src4[i];
            vv.x *= sc; vv.y *= sc; vv.z *= sc; vv.w *= sc;
            dst4[i] = vv;
        }
    }
}

// ============================================================================
// Kernel B: out = attn_p @ V. QB=64 block, 4q x 4d per thread, 3 CTAs/SM.
// ============================================================================
#define QB 64
#define PADB 68
#define KSTEP 64
#define NKT (NSEQ/KSTEP)
#define STAGE_F (QB*PADB + KSTEP*PADB)

__global__ __launch_bounds__(256, 3)
void pv_kernel(const float* __restrict__ attn,
               const float* __restrict__ v,
               float* __restrict__ out) {
    extern __shared__ float smb[];
    const int tid = threadIdx.x;
    const int tx = tid & 15;       // d cols 4*tx..
    const int ty = tid >> 4;       // q rows 4*ty..
    const int bh = blockIdx.y;
    const int row0 = blockIdx.x * QB;
    const size_t abase = ((size_t)bh * NSEQ + row0) * NSEQ;
    const size_t vbase = (size_t)bh * NSEQ * DDIM;
    const unsigned smbu = (unsigned)__cvta_generic_to_shared(smb);

    auto issue_stage = [&](int t, int buf) {
        unsigned pbase = smbu + 4u*buf*STAGE_F;
        unsigned vbse  = pbase + 4u*QB*PADB;
        #pragma unroll
        for (int j = 0; j < 4; j++) {
            int idx = tid + j*256;             // 0..1023
            int rr = idx >> 4, c4 = idx & 15;
            cpa16(pbase + 4u*(rr*PADB + c4*4),
                  attn + abase + (size_t)rr*NSEQ + t*KSTEP + c4*4);
            cpa16(vbse + 4u*(rr*PADB + c4*4),
                  v + vbase + (size_t)(t*KSTEP + rr)*DDIM + c4*4);
        }
        cp_commit();
    };

    u64 acc[4][2];
    #pragma unroll
    for (int i = 0; i < 4; i++) { acc[i][0] = 0ull; acc[i][1] = 0ull; }

    issue_stage(0, 0);
    for (int t = 0; t < NKT; t++) {
        if (t + 1 < NKT) { issue_stage(t + 1, (t + 1) & 1); cp_wait1(); }
        else cp_wait0();
        __syncthreads();
        const float* Pt = smb + (t & 1)*STAGE_F;
        const float* Vt = Pt + QB*PADB;
        #pragma unroll 4
        for (int kg = 0; kg < KSTEP/4; kg++) {
            int k0 = kg*4;
            float4 v0 = *(const float4*)&Vt[(k0+0)*PADB + tx*4];
            float4 v1 = *(const float4*)&Vt[(k0+1)*PADB + tx*4];
            float4 v2 = *(const float4*)&Vt[(k0+2)*PADB + tx*4];
            float4 v3 = *(const float4*)&Vt[(k0+3)*PADB + tx*4];
            u64 v0l = pk2(v0.x,v0.y), v0h = pk2(v0.z,v0.w);
            u64 v1l = pk2(v1.x,v1.y), v1h = pk2(v1.z,v1.w);
            u64 v2l = pk2(v2.x,v2.y), v2h = pk2(v2.z,v2.w);
            u64 v3l = pk2(v3.x,v3.y), v3h = pk2(v3.z,v3.w);
            #pragma unroll
            for (int i = 0; i < 4; i++) {
                float4 p = *(const float4*)&Pt[(ty*4+i)*PADB + k0];
                fma2(acc[i][0], pk2(p.x,p.x), v0l); fma2(acc[i][1], pk2(p.x,p.x), v0h);
                fma2(acc[i][0], pk2(p.y,p.y), v1l); fma2(acc[i][1], pk2(p.y,p.y), v1h);
                fma2(acc[i][0], pk2(p.z,p.z), v2l); fma2(acc[i][1], pk2(p.z,p.z), v2h);
                fma2(acc[i][0], pk2(p.w,p.w), v3l); fma2(acc[i][1], pk2(p.w,p.w), v3h);
            }
        }
        __syncthreads();
    }

    #pragma unroll
    for (int i = 0; i < 4; i++) {
        float2 lo = up2(acc[i][0]), hi = up2(acc[i][1]);
        float4 r; r.x = lo.x; r.y = lo.y; r.z = hi.x; r.w = hi.y;
        *(float4*)&out[((size_t)bh*NSEQ + row0 + ty*4 + i)*DDIM + tx*4] = r;
    }
}

extern "C" void kernel_launch(void* const* d_in, const int* in_sizes, int n_in,
                              void* d_out, int out_size) {
    const float* q = (const float*)d_in[0];
    const float* k = (const float*)d_in[1];
    const float* v = (const float*)d_in[2];
    float* out = (float*)d_out;                                 // [B,H,N,D]
    float* attn_out = out + (size_t)B_ * H_ * NSEQ * DDIM;      // [B,H,N,N]

    dim3 gridT(NSEQ/32, DDIM/32, BH);
    transpose_k<<<gridT, dim3(32, 8)>>>(k);

    const int smemA = S_F*4 + QP_U*8 + KTS_F*4 + ROWS*8 + ROWS*4;
    cudaFuncSetAttribute(sdpa_scores_kernel,
                         cudaFuncAttributeMaxDynamicSharedMemorySize, smemA);
    dim3 gridA(NSEQ / ROWS, BH);
    sdpa_scores_kernel<<<gridA, NTA, smemA>>>(q, attn_out);

    const int smemB = 2 * STAGE_F * 4;
    cudaFuncSetAttribute(pv_kernel,
                         cudaFuncAttributeMaxDynamicSharedMemorySize, smemB);
    dim3 gridB(NSEQ / QB, BH);
    pv_kernel<<<gridB, 256, smemB>>>(attn_out, v, out);
}